// round 6
// baseline (speedup 1.0000x reference)
#include <cuda_runtime.h>
#include <cuda_fp16.h>
#include <cstdint>

#define B_ 8
#define C_ 256
#define H_ 128
#define W_ 128
#define HW_ (H_*W_)            // 16384
#define NPLANE (B_*C_)         // 2048
#define K_ 1280
#define O_ 256

#define NEG_INF __int_as_float(0xff800000)

// fp16 scratch: x copy + 4 directional-max tensors + transposed weights.
__device__ __half g_x16[NPLANE*HW_];
__device__ __half g_dir16[4][NPLANE*HW_];
__device__ __half g_wT16[K_*O_];

// ------------------------------------------------------------------
// helpers
// ------------------------------------------------------------------
__device__ __forceinline__ uint32_t smem_u32(const void* p) {
    return (uint32_t)__cvta_generic_to_shared(p);
}
__device__ __forceinline__ void cp16(uint32_t s, const void* g) {
    asm volatile("cp.async.cg.shared.global [%0], [%1], 16;\n" :: "r"(s), "l"(g));
}
__device__ __forceinline__ void ldsm_x4_t(uint32_t& d0, uint32_t& d1,
                                          uint32_t& d2, uint32_t& d3, uint32_t a) {
    asm volatile("ldmatrix.sync.aligned.m8n8.x4.trans.shared.b16 {%0,%1,%2,%3},[%4];\n"
                 : "=r"(d0), "=r"(d1), "=r"(d2), "=r"(d3) : "r"(a));
}
__device__ __forceinline__ void mma_f16(float* d, const uint32_t* a, const uint32_t* b) {
    asm volatile(
        "mma.sync.aligned.m16n8k16.row.col.f32.f16.f16.f32 "
        "{%0,%1,%2,%3},{%4,%5,%6,%7},{%8,%9},{%0,%1,%2,%3};"
        : "+f"(d[0]), "+f"(d[1]), "+f"(d[2]), "+f"(d[3])
        : "r"(a[0]), "r"(a[1]), "r"(a[2]), "r"(a[3]), "r"(b[0]), "r"(b[1]));
}

// ------------------------------------------------------------------
// kernel 0: transpose conv_w [O][K] -> wT16 [K][O]
// ------------------------------------------------------------------
__global__ void k_wt(const float* __restrict__ w) {
    int idx = blockIdx.x * 256 + threadIdx.x;
    if (idx < K_*O_) {
        int o = idx / K_;
        int k = idx - o*K_;
        g_wT16[k*O_ + o] = __float2half_rn(w[idx]);
    }
}

// ------------------------------------------------------------------
// kernel 1: directional maxes -> fp16 scratch. One CTA per (b,c) plane.
// ------------------------------------------------------------------
#define DIR_SMEM (H_*(W_+1)*4)

__global__ void __launch_bounds__(256) k_dir(const float* __restrict__ x) {
    extern __shared__ float sp[];      // [H_][W_+1]
    const int LDSP = W_ + 1;           // 129
    int plane = blockIdx.x;
    const float* src = x + (size_t)plane*HW_;
    __half* x16 = g_x16 + (size_t)plane*HW_;
    int tid = threadIdx.x;

    for (int i = tid; i < HW_; i += 256) {
        float v = src[i];
        sp[(i >> 7)*LDSP + (i & 127)] = v;
        x16[i] = __float2half_rn(v);
    }
    __syncthreads();

    // ---- H-direction: threads 0..127 prefix, 128..255 suffix ----
    {
        int w = tid & 127;
        float m = NEG_INF;
        if (tid < 128) {
            __half* dst = g_dir16[0] + (size_t)plane*HW_;
            #pragma unroll 8
            for (int h = 0; h < H_; ++h) {
                m = fmaxf(m, sp[h*LDSP + w]);
                dst[h*W_ + w] = __float2half_rn(m);
            }
        } else {
            __half* dst = g_dir16[1] + (size_t)plane*HW_;
            #pragma unroll 8
            for (int h = H_-1; h >= 0; --h) {
                m = fmaxf(m, sp[h*LDSP + w]);
                dst[h*W_ + w] = __float2half_rn(m);
            }
        }
    }

    // ---- W-direction: warp per row via shuffle scans ----
    int warp = tid >> 5, lane = tid & 31;
    __half* d2 = g_dir16[2] + (size_t)plane*HW_;
    __half* d3 = g_dir16[3] + (size_t)plane*HW_;
    for (int r = 0; r < 16; ++r) {
        int h = warp*16 + r;
        const float* row = sp + h*LDSP + 4*lane;
        float v0 = row[0], v1 = row[1], v2 = row[2], v3 = row[3];

        float p0 = v0, p1 = fmaxf(v1,p0), p2 = fmaxf(v2,p1), p3 = fmaxf(v3,p2);
        float agg = p3;
        #pragma unroll
        for (int d = 1; d < 32; d <<= 1) {
            float t = __shfl_up_sync(0xffffffffu, agg, d);
            if (lane >= d) agg = fmaxf(agg, t);
        }
        float prev = __shfl_up_sync(0xffffffffu, agg, 1);
        if (lane == 0) prev = NEG_INF;
        __half2 P01 = __floats2half2_rn(fmaxf(p0,prev), fmaxf(p1,prev));
        __half2 P23 = __floats2half2_rn(fmaxf(p2,prev), fmaxf(p3,prev));
        *reinterpret_cast<__half2*>(d2 + h*W_ + 4*lane)     = P01;
        *reinterpret_cast<__half2*>(d2 + h*W_ + 4*lane + 2) = P23;

        float s3 = v3, s2 = fmaxf(v2,s3), s1 = fmaxf(v1,s2), s0 = fmaxf(v0,s1);
        float agg2 = s0;
        #pragma unroll
        for (int d = 1; d < 32; d <<= 1) {
            float t = __shfl_down_sync(0xffffffffu, agg2, d);
            if (lane + d < 32) agg2 = fmaxf(agg2, t);
        }
        float nxt = __shfl_down_sync(0xffffffffu, agg2, 1);
        if (lane == 31) nxt = NEG_INF;
        __half2 S01 = __floats2half2_rn(fmaxf(s0,nxt), fmaxf(s1,nxt));
        __half2 S23 = __floats2half2_rn(fmaxf(s2,nxt), fmaxf(s3,nxt));
        *reinterpret_cast<__half2*>(d3 + h*W_ + 4*lane)     = S01;
        *reinterpret_cast<__half2*>(d3 + h*W_ + 4*lane + 2) = S23;
    }
}

// ------------------------------------------------------------------
// kernel 2: fp16 GEMM  out[b][o][p] = sum_k A16[b][k][p] * wT16[k][o] + bias[o]
// BM=128 pixels, BN=256 outs (A read ONCE), BK=32, 256 threads, warp tile 64x64.
// 3-stage cp.async pipeline; all LDSM for a k-tile hoisted ahead of the MMAs.
// ------------------------------------------------------------------
#define BM 128
#define BN 256
#define BK 32
#define STAGES 3
#define SA_LD 136   // halves: 272B row -> k-rows shift across 16B groups (LDSM conflict-free)
#define SB_LD 264
#define STG_HALVES (BK*SA_LD + BK*SB_LD)
#define GEMM_SMEM (STAGES*STG_HALVES*2)   // 76800 B

__global__ void __launch_bounds__(256, 1) k_gemm(const float* __restrict__ bias,
                                                 float* __restrict__ out) {
    extern __shared__ __half sm[];

    int tid  = threadIdx.x;
    int lane = tid & 31, warp = tid >> 5;
    int wm = warp >> 2, wn = warp & 3;       // 2 x 4 warp grid -> 64x64 warp tiles
    int grp = lane >> 2, tig = lane & 3;
    int lr = lane & 7, lg = lane >> 3;       // ldmatrix row / matrix-group

    int pixbase = blockIdx.x * BM;
    int b       = blockIdx.y;

    size_t boff = (size_t)b * C_ * HW_;
    const __half* srcs[5] = { g_x16 + boff, g_dir16[0] + boff, g_dir16[1] + boff,
                              g_dir16[2] + boff, g_dir16[3] + boff };

    auto load_tile = [&](int kt, int st) {
        int region = kt >> 3;                 // 5 regions of 8 k-tiles
        int c0 = (kt & 7) * BK;
        const __half* aptr = srcs[region] + (size_t)c0*HW_ + pixbase;
        const __half* bptr = g_wT16 + (size_t)(kt*BK)*O_;
        __half* sa = sm + st*STG_HALVES;
        __half* sb = sa + BK*SA_LD;
        #pragma unroll
        for (int i = 0; i < 2; ++i) {         // A: 32 rows x 256B
            int c  = tid + i*256;
            int kr = c >> 4, cc = c & 15;
            cp16(smem_u32(sa + kr*SA_LD + cc*8), aptr + (size_t)kr*HW_ + cc*8);
        }
        #pragma unroll
        for (int i = 0; i < 4; ++i) {         // B: 32 rows x 512B
            int c  = tid + i*256;
            int kr = c >> 5, cc = c & 31;
            cp16(smem_u32(sb + kr*SB_LD + cc*8), bptr + kr*O_ + cc*8);
        }
        asm volatile("cp.async.commit_group;\n" ::: "memory");
    };

    float acc[4][8][4];
    #pragma unroll
    for (int i = 0; i < 4; ++i)
        #pragma unroll
        for (int j = 0; j < 8; ++j)
            #pragma unroll
            for (int r = 0; r < 4; ++r) acc[i][j][r] = 0.f;

    load_tile(0, 0);
    load_tile(1, 1);

    for (int kt = 0; kt < 40; ++kt) {
        int cur = kt % STAGES;
        if (kt + 2 < 40) {
            load_tile(kt + 2, (kt + 2) % STAGES);
            asm volatile("cp.async.wait_group 2;\n" ::: "memory");
        } else {
            asm volatile("cp.async.wait_group %0;\n" :: "n"(0) : "memory");
        }
        __syncthreads();

        uint32_t saU = smem_u32(sm + cur*STG_HALVES);
        uint32_t sbU = saU + BK*SA_LD*2;

        // ---- hoist ALL fragment loads for both k-phases ----
        uint32_t af[2][4][4];
        uint32_t bf[2][8][2];
        #pragma unroll
        for (int s = 0; s < 2; ++s) {
            int k0 = s*16;
            {
                int krow = k0 + lr + ((lg & 2) << 2);
                int cofs = (lg & 1) << 3;
                #pragma unroll
                for (int mf = 0; mf < 4; ++mf) {
                    int m0 = wm*64 + mf*16;
                    uint32_t a = saU + (uint32_t)(krow*SA_LD + m0 + cofs)*2;
                    ldsm_x4_t(af[s][mf][0], af[s][mf][1], af[s][mf][2], af[s][mf][3], a);
                }
            }
            {
                int krow = k0 + lr + ((lg & 1) << 3);
                int cofs = (lg >> 1) << 3;
                #pragma unroll
                for (int jp = 0; jp < 4; ++jp) {
                    int nj = wn*64 + jp*16;
                    uint32_t a = sbU + (uint32_t)(krow*SB_LD + nj + cofs)*2;
                    ldsm_x4_t(bf[s][2*jp][0], bf[s][2*jp][1],
                              bf[s][2*jp+1][0], bf[s][2*jp+1][1], a);
                }
            }
        }
        #pragma unroll
        for (int s = 0; s < 2; ++s)
            #pragma unroll
            for (int mf = 0; mf < 4; ++mf)
                #pragma unroll
                for (int nf = 0; nf < 8; ++nf)
                    mma_f16(acc[mf][nf], af[s][mf], bf[s][nf]);
        __syncthreads();
    }

    // epilogue: +bias, store fp32
    float* outb = out + (size_t)b * O_ * HW_;
    #pragma unroll
    for (int nf = 0; nf < 8; ++nf) {
        int o = wn*64 + nf*8 + tig*2;
        float bv0 = bias[o], bv1 = bias[o+1];
        #pragma unroll
        for (int mf = 0; mf < 4; ++mf) {
            int m = pixbase + wm*64 + mf*16 + grp;
            outb[(size_t)o*HW_ + m]         = acc[mf][nf][0] + bv0;
            outb[(size_t)(o+1)*HW_ + m]     = acc[mf][nf][1] + bv1;
            outb[(size_t)o*HW_ + m + 8]     = acc[mf][nf][2] + bv0;
            outb[(size_t)(o+1)*HW_ + m + 8] = acc[mf][nf][3] + bv1;
        }
    }
}

// ------------------------------------------------------------------
extern "C" void kernel_launch(void* const* d_in, const int* in_sizes, int n_in,
                              void* d_out, int out_size) {
    (void)in_sizes; (void)n_in; (void)out_size;
    const float* x    = (const float*)d_in[0];
    const float* w    = (const float*)d_in[1];
    const float* bias = (const float*)d_in[2];
    float* out = (float*)d_out;

    cudaFuncSetAttribute(k_dir,  cudaFuncAttributeMaxDynamicSharedMemorySize, DIR_SMEM);
    cudaFuncSetAttribute(k_gemm, cudaFuncAttributeMaxDynamicSharedMemorySize, GEMM_SMEM);

    k_wt<<<(K_*O_ + 255)/256, 256>>>(w);
    k_dir<<<NPLANE, 256, DIR_SMEM>>>(x);

    dim3 grid(HW_/BM, B_);   // (128, 8)
    k_gemm<<<grid, 256, GEMM_SMEM>>>(bias, out);
}

// round 7
// speedup vs baseline: 1.0210x; 1.0210x over previous
#include <cuda_runtime.h>
#include <cuda_fp16.h>
#include <cstdint>

#define B_ 8
#define C_ 256
#define H_ 128
#define W_ 128
#define HW_ (H_*W_)            // 16384
#define NPLANE (B_*C_)         // 2048
#define K_ 1280
#define O_ 256

#define NEG_INF __int_as_float(0xff800000)

// fp16 scratch: x copy + 4 directional-max tensors + transposed weights.
__device__ __half g_x16[NPLANE*HW_];
__device__ __half g_dir16[4][NPLANE*HW_];
__device__ __half g_wT16[K_*O_];

// ------------------------------------------------------------------
// helpers
// ------------------------------------------------------------------
__device__ __forceinline__ uint32_t smem_u32(const void* p) {
    return (uint32_t)__cvta_generic_to_shared(p);
}
__device__ __forceinline__ void cp16(uint32_t s, const void* g) {
    asm volatile("cp.async.cg.shared.global [%0], [%1], 16;\n" :: "r"(s), "l"(g));
}
__device__ __forceinline__ void ldsm_x4_t(uint32_t& d0, uint32_t& d1,
                                          uint32_t& d2, uint32_t& d3, uint32_t a) {
    asm volatile("ldmatrix.sync.aligned.m8n8.x4.trans.shared.b16 {%0,%1,%2,%3},[%4];\n"
                 : "=r"(d0), "=r"(d1), "=r"(d2), "=r"(d3) : "r"(a));
}
__device__ __forceinline__ void mma_f16(float* d, const uint32_t* a, const uint32_t* b) {
    asm volatile(
        "mma.sync.aligned.m16n8k16.row.col.f32.f16.f16.f32 "
        "{%0,%1,%2,%3},{%4,%5,%6,%7},{%8,%9},{%0,%1,%2,%3};"
        : "+f"(d[0]), "+f"(d[1]), "+f"(d[2]), "+f"(d[3])
        : "r"(a[0]), "r"(a[1]), "r"(a[2]), "r"(a[3]), "r"(b[0]), "r"(b[1]));
}

// ------------------------------------------------------------------
// kernel 0: transpose conv_w [O][K] -> wT16 [K][O]
// ------------------------------------------------------------------
__global__ void k_wt(const float* __restrict__ w) {
    int idx = blockIdx.x * 256 + threadIdx.x;
    if (idx < K_*O_) {
        int o = idx / K_;
        int k = idx - o*K_;
        g_wT16[k*O_ + o] = __float2half_rn(w[idx]);
    }
}

// ------------------------------------------------------------------
// kernel 1: directional maxes for ONE batch (256 planes) -> fp16 scratch.
// ------------------------------------------------------------------
#define DIR_SMEM (H_*(W_+1)*4)

__global__ void __launch_bounds__(256) k_dir(const float* __restrict__ x, int b) {
    extern __shared__ float sp[];      // [H_][W_+1]
    const int LDSP = W_ + 1;           // 129
    int plane = b*C_ + blockIdx.x;
    const float* src = x + (size_t)plane*HW_;
    __half* x16 = g_x16 + (size_t)plane*HW_;
    int tid = threadIdx.x;

    for (int i = tid; i < HW_; i += 256) {
        float v = src[i];
        sp[(i >> 7)*LDSP + (i & 127)] = v;
        x16[i] = __float2half_rn(v);
    }
    __syncthreads();

    // ---- H-direction: threads 0..127 prefix, 128..255 suffix ----
    {
        int w = tid & 127;
        float m = NEG_INF;
        if (tid < 128) {
            __half* dst = g_dir16[0] + (size_t)plane*HW_;
            #pragma unroll 8
            for (int h = 0; h < H_; ++h) {
                m = fmaxf(m, sp[h*LDSP + w]);
                dst[h*W_ + w] = __float2half_rn(m);
            }
        } else {
            __half* dst = g_dir16[1] + (size_t)plane*HW_;
            #pragma unroll 8
            for (int h = H_-1; h >= 0; --h) {
                m = fmaxf(m, sp[h*LDSP + w]);
                dst[h*W_ + w] = __float2half_rn(m);
            }
        }
    }

    // ---- W-direction: warp per row via shuffle scans ----
    int warp = tid >> 5, lane = tid & 31;
    __half* d2 = g_dir16[2] + (size_t)plane*HW_;
    __half* d3 = g_dir16[3] + (size_t)plane*HW_;
    for (int r = 0; r < 16; ++r) {
        int h = warp*16 + r;
        const float* row = sp + h*LDSP + 4*lane;
        float v0 = row[0], v1 = row[1], v2 = row[2], v3 = row[3];

        float p0 = v0, p1 = fmaxf(v1,p0), p2 = fmaxf(v2,p1), p3 = fmaxf(v3,p2);
        float agg = p3;
        #pragma unroll
        for (int d = 1; d < 32; d <<= 1) {
            float t = __shfl_up_sync(0xffffffffu, agg, d);
            if (lane >= d) agg = fmaxf(agg, t);
        }
        float prev = __shfl_up_sync(0xffffffffu, agg, 1);
        if (lane == 0) prev = NEG_INF;
        __half2 P01 = __floats2half2_rn(fmaxf(p0,prev), fmaxf(p1,prev));
        __half2 P23 = __floats2half2_rn(fmaxf(p2,prev), fmaxf(p3,prev));
        *reinterpret_cast<__half2*>(d2 + h*W_ + 4*lane)     = P01;
        *reinterpret_cast<__half2*>(d2 + h*W_ + 4*lane + 2) = P23;

        float s3 = v3, s2 = fmaxf(v2,s3), s1 = fmaxf(v1,s2), s0 = fmaxf(v0,s1);
        float agg2 = s0;
        #pragma unroll
        for (int d = 1; d < 32; d <<= 1) {
            float t = __shfl_down_sync(0xffffffffu, agg2, d);
            if (lane + d < 32) agg2 = fmaxf(agg2, t);
        }
        float nxt = __shfl_down_sync(0xffffffffu, agg2, 1);
        if (lane == 31) nxt = NEG_INF;
        __half2 S01 = __floats2half2_rn(fmaxf(s0,nxt), fmaxf(s1,nxt));
        __half2 S23 = __floats2half2_rn(fmaxf(s2,nxt), fmaxf(s3,nxt));
        *reinterpret_cast<__half2*>(d3 + h*W_ + 4*lane)     = S01;
        *reinterpret_cast<__half2*>(d3 + h*W_ + 4*lane + 2) = S23;
    }
}

// ------------------------------------------------------------------
// kernel 2: fp16 GEMM for ONE batch.
// BM=128 pixels, BN=256 outs, BK=32, 256 threads, warp tile 64x64, 3 stages.
// ------------------------------------------------------------------
#define BM 128
#define BN 256
#define BK 32
#define STAGES 3
#define SA_LD 136
#define SB_LD 264
#define STG_HALVES (BK*SA_LD + BK*SB_LD)
#define GEMM_SMEM (STAGES*STG_HALVES*2)   // 76800 B

__global__ void __launch_bounds__(256, 1) k_gemm(const float* __restrict__ bias,
                                                 float* __restrict__ out, int b) {
    extern __shared__ __half sm[];

    int tid  = threadIdx.x;
    int lane = tid & 31, warp = tid >> 5;
    int wm = warp >> 2, wn = warp & 3;
    int grp = lane >> 2, tig = lane & 3;
    int lr = lane & 7, lg = lane >> 3;

    int pixbase = blockIdx.x * BM;

    size_t boff = (size_t)b * C_ * HW_;
    const __half* srcs[5] = { g_x16 + boff, g_dir16[0] + boff, g_dir16[1] + boff,
                              g_dir16[2] + boff, g_dir16[3] + boff };

    auto load_tile = [&](int kt, int st) {
        int region = kt >> 3;
        int c0 = (kt & 7) * BK;
        const __half* aptr = srcs[region] + (size_t)c0*HW_ + pixbase;
        const __half* bptr = g_wT16 + (size_t)(kt*BK)*O_;
        __half* sa = sm + st*STG_HALVES;
        __half* sb = sa + BK*SA_LD;
        #pragma unroll
        for (int i = 0; i < 2; ++i) {
            int c  = tid + i*256;
            int kr = c >> 4, cc = c & 15;
            cp16(smem_u32(sa + kr*SA_LD + cc*8), aptr + (size_t)kr*HW_ + cc*8);
        }
        #pragma unroll
        for (int i = 0; i < 4; ++i) {
            int c  = tid + i*256;
            int kr = c >> 5, cc = c & 31;
            cp16(smem_u32(sb + kr*SB_LD + cc*8), bptr + kr*O_ + cc*8);
        }
        asm volatile("cp.async.commit_group;\n" ::: "memory");
    };

    float acc[4][8][4];
    #pragma unroll
    for (int i = 0; i < 4; ++i)
        #pragma unroll
        for (int j = 0; j < 8; ++j)
            #pragma unroll
            for (int r = 0; r < 4; ++r) acc[i][j][r] = 0.f;

    load_tile(0, 0);
    load_tile(1, 1);

    for (int kt = 0; kt < 40; ++kt) {
        int cur = kt % STAGES;
        if (kt + 2 < 40) {
            load_tile(kt + 2, (kt + 2) % STAGES);
            asm volatile("cp.async.wait_group 2;\n" ::: "memory");
        } else {
            asm volatile("cp.async.wait_group %0;\n" :: "n"(0) : "memory");
        }
        __syncthreads();

        uint32_t saU = smem_u32(sm + cur*STG_HALVES);
        uint32_t sbU = saU + BK*SA_LD*2;

        uint32_t af[2][4][4];
        uint32_t bf[2][8][2];
        #pragma unroll
        for (int s = 0; s < 2; ++s) {
            int k0 = s*16;
            {
                int krow = k0 + lr + ((lg & 2) << 2);
                int cofs = (lg & 1) << 3;
                #pragma unroll
                for (int mf = 0; mf < 4; ++mf) {
                    int m0 = wm*64 + mf*16;
                    uint32_t a = saU + (uint32_t)(krow*SA_LD + m0 + cofs)*2;
                    ldsm_x4_t(af[s][mf][0], af[s][mf][1], af[s][mf][2], af[s][mf][3], a);
                }
            }
            {
                int krow = k0 + lr + ((lg & 1) << 3);
                int cofs = (lg >> 1) << 3;
                #pragma unroll
                for (int jp = 0; jp < 4; ++jp) {
                    int nj = wn*64 + jp*16;
                    uint32_t a = sbU + (uint32_t)(krow*SB_LD + nj + cofs)*2;
                    ldsm_x4_t(bf[s][2*jp][0], bf[s][2*jp][1],
                              bf[s][2*jp+1][0], bf[s][2*jp+1][1], a);
                }
            }
        }
        #pragma unroll
        for (int s = 0; s < 2; ++s)
            #pragma unroll
            for (int mf = 0; mf < 4; ++mf)
                #pragma unroll
                for (int nf = 0; nf < 8; ++nf)
                    mma_f16(acc[mf][nf], af[s][mf], bf[s][nf]);
        __syncthreads();
    }

    float* outb = out + (size_t)b * O_ * HW_;
    #pragma unroll
    for (int nf = 0; nf < 8; ++nf) {
        int o = wn*64 + nf*8 + tig*2;
        float bv0 = bias[o], bv1 = bias[o+1];
        #pragma unroll
        for (int mf = 0; mf < 4; ++mf) {
            int m = pixbase + wm*64 + mf*16 + grp;
            outb[(size_t)o*HW_ + m]         = acc[mf][nf][0] + bv0;
            outb[(size_t)(o+1)*HW_ + m]     = acc[mf][nf][1] + bv1;
            outb[(size_t)o*HW_ + m + 8]     = acc[mf][nf][2] + bv0;
            outb[(size_t)(o+1)*HW_ + m + 8] = acc[mf][nf][3] + bv1;
        }
    }
}

// ------------------------------------------------------------------
// launch: fork-join capture. dir stream feeds per-batch gemms on two
// alternating gemm streams; all deps expressed via events (capture-legal).
// Streams/events are created lazily once (host-side cache only; the device
// work per call is identical every call).
// ------------------------------------------------------------------
extern "C" void kernel_launch(void* const* d_in, const int* in_sizes, int n_in,
                              void* d_out, int out_size) {
    (void)in_sizes; (void)n_in; (void)out_size;
    const float* x    = (const float*)d_in[0];
    const float* w    = (const float*)d_in[1];
    const float* bias = (const float*)d_in[2];
    float* out = (float*)d_out;

    static cudaStream_t sDir = nullptr, sG = nullptr;
    static cudaEvent_t evFork, evJoin, evD[B_];
    if (!sDir) {
        cudaStreamCreateWithFlags(&sDir, cudaStreamNonBlocking);
        cudaStreamCreateWithFlags(&sG,   cudaStreamNonBlocking);
        cudaEventCreateWithFlags(&evFork, cudaEventDisableTiming);
        cudaEventCreateWithFlags(&evJoin, cudaEventDisableTiming);
        for (int b = 0; b < B_; ++b)
            cudaEventCreateWithFlags(&evD[b], cudaEventDisableTiming);
        cudaFuncSetAttribute(k_dir,  cudaFuncAttributeMaxDynamicSharedMemorySize, DIR_SMEM);
        cudaFuncSetAttribute(k_gemm, cudaFuncAttributeMaxDynamicSharedMemorySize, GEMM_SMEM);
    }

    // weights on the capture (default) stream
    k_wt<<<(K_*O_ + 255)/256, 256>>>(w);

    // fork
    cudaEventRecord(evFork, 0);
    cudaStreamWaitEvent(sDir, evFork, 0);
    cudaStreamWaitEvent(sG,   evFork, 0);

    // per-batch dir chain on sDir
    for (int b = 0; b < B_; ++b) {
        k_dir<<<C_, 256, DIR_SMEM, sDir>>>(x, b);
        cudaEventRecord(evD[b], sDir);
    }

    // per-batch gemms alternating between default stream and sG
    for (int b = 0; b < B_; ++b) {
        cudaStream_t st = (b & 1) ? sG : (cudaStream_t)0;
        cudaStreamWaitEvent(st, evD[b], 0);
        k_gemm<<<HW_/BM, 256, GEMM_SMEM, st>>>(bias, out, b);
    }

    // join sG back into the capture stream
    cudaEventRecord(evJoin, sG);
    cudaStreamWaitEvent(0, evJoin, 0);
}